// round 14
// baseline (speedup 1.0000x reference)
#include <cuda_runtime.h>
#include <cuda_fp16.h>
#include <math.h>

// ---------------------------------------------------------------------------
// AGNN — fp16 normalized features; pair-blocked gemm1/final (R13);
// B-buffer zeroing folded into edge-0 prologue (1 float/thread).
// ---------------------------------------------------------------------------

#define NN 100000
#define NE 1600000
#define EPSF 1e-12f
#define FULLM 0xFFFFFFFFu

__device__ __align__(128) float  g_aggA[NN * 32];
__device__ __align__(128) float  g_aggB[NN * 32];
__device__ __align__(128) __half g_hnA[NN * 32];
__device__ __align__(128) __half g_hnB[NN * 32];
__device__ __align__(128) float  g_norm[NN];
__device__ __align__(128) float  g_denomA[NN];
__device__ __align__(128) float  g_denomB[NN];

// ---------------------------------------------------------------------------
// Zero ONLY the layer-0 accumulators (aggA/denA).
__global__ void k_zero_A(float4* __restrict__ aggA, float4* __restrict__ denA,
                         int n_agg4, int n_den4) {
    int i = blockIdx.x * blockDim.x + threadIdx.x;
    float4 z = make_float4(0.f, 0.f, 0.f, 0.f);
    if (i < n_agg4) aggA[i] = z;
    if (i < n_den4) denA[i] = z;
}

// ---------------------------------------------------------------------------
// GEMM1, pair-blocked (R13 exact).
__global__ __launch_bounds__(256) void k_gemm1(
    const float* __restrict__ feat, const float* __restrict__ w1,
    const float* __restrict__ b1, __half* __restrict__ hn,
    float* __restrict__ normv, int n)
{
    __shared__ float w1t[128 * 32];   // [k][j]
    __shared__ float b1s[32];
    for (int i = threadIdx.x; i < 4096; i += 256) {
        int j = i >> 7, k = i & 127;
        w1t[k * 32 + j] = w1[i];
    }
    if (threadIdx.x < 32) b1s[threadIdx.x] = b1[threadIdx.x];
    __syncthreads();

    int gid  = blockIdx.x * 256 + threadIdx.x;
    int pair = gid >> 1;
    int jh   = gid & 1;
    int n0   = pair * 2;
    int n1   = n0 + 1;
    if (n0 >= n) return;
    bool has1 = (n1 < n);

    float acc0[16], acc1[16];
    #pragma unroll
    for (int j = 0; j < 16; j++) {
        float b = b1s[jh * 16 + j];
        acc0[j] = b; acc1[j] = b;
    }

    const float4* f0 = reinterpret_cast<const float4*>(feat + (size_t)n0 * 128);
    const float4* f1 = reinterpret_cast<const float4*>(feat + (size_t)(has1 ? n1 : n0) * 128);

    #pragma unroll 4
    for (int k4 = 0; k4 < 32; k4++) {
        float4 fa = f0[k4];
        float4 fb = f1[k4];
        float fv0[4] = {fa.x, fa.y, fa.z, fa.w};
        float fv1[4] = {fb.x, fb.y, fb.z, fb.w};
        #pragma unroll
        for (int c = 0; c < 4; c++) {
            const float4* w4 = reinterpret_cast<const float4*>(
                &w1t[(k4 * 4 + c) * 32 + jh * 16]);
            #pragma unroll
            for (int j4 = 0; j4 < 4; j4++) {
                float4 w = w4[j4];
                acc0[j4*4+0] += fv0[c]*w.x; acc0[j4*4+1] += fv0[c]*w.y;
                acc0[j4*4+2] += fv0[c]*w.z; acc0[j4*4+3] += fv0[c]*w.w;
                acc1[j4*4+0] += fv1[c]*w.x; acc1[j4*4+1] += fv1[c]*w.y;
                acc1[j4*4+2] += fv1[c]*w.z; acc1[j4*4+3] += fv1[c]*w.w;
            }
        }
    }

    float ss0 = 0.f, ss1 = 0.f;
    #pragma unroll
    for (int j = 0; j < 16; j++) {
        float v0 = fmaxf(acc0[j], 0.f); acc0[j] = v0; ss0 += v0 * v0;
        float v1 = fmaxf(acc1[j], 0.f); acc1[j] = v1; ss1 += v1 * v1;
    }
    ss0 += __shfl_xor_sync(FULLM, ss0, 1);
    ss1 += __shfl_xor_sync(FULLM, ss1, 1);

    float nv0 = fmaxf(sqrtf(ss0), EPSF), rinv0 = 1.0f / nv0;
    float nv1 = fmaxf(sqrtf(ss1), EPSF), rinv1 = 1.0f / nv1;
    if (jh == 0) {
        normv[n0] = nv0;
        if (has1) normv[n1] = nv1;
    }

    __half2 hp0[8], hp1[8];
    #pragma unroll
    for (int j = 0; j < 8; j++) {
        hp0[j] = __floats2half2_rn(acc0[2*j] * rinv0, acc0[2*j+1] * rinv0);
        hp1[j] = __floats2half2_rn(acc1[2*j] * rinv1, acc1[2*j+1] * rinv1);
    }
    uint4* o0 = reinterpret_cast<uint4*>(hn + (size_t)n0 * 32 + jh * 16);
    o0[0] = reinterpret_cast<const uint4*>(hp0)[0];
    o0[1] = reinterpret_cast<const uint4*>(hp0)[1];
    if (has1) {
        uint4* o1 = reinterpret_cast<uint4*>(hn + (size_t)n1 * 32 + jh * 16);
        o1[0] = reinterpret_cast<const uint4*>(hp1)[0];
        o1[1] = reinterpret_cast<const uint4*>(hp1)[1];
    }
}

// ---------------------------------------------------------------------------
// Fused edge pass: 8 lanes/edge, 4 edges/group, HFMA2 dot.
// If zero_agg != nullptr: each thread zeroes one float of zero_agg (and the
// first n threads zero zero_den) BEFORE its edge work (layer-0 call zeroes
// the layer-1 buffers; they are first consumed only after this kernel ends).
__global__ __launch_bounds__(256) void k_edge_fused(
    const int* __restrict__ src, const int* __restrict__ dst,
    const __half* __restrict__ hn, const float* __restrict__ normv,
    const float* __restrict__ betas, int layer,
    float* __restrict__ denom, float* __restrict__ agg,
    float* __restrict__ zero_agg, float* __restrict__ zero_den,
    int n, int ne)
{
    int gid   = blockIdx.x * 256 + threadIdx.x;

    if (zero_agg) {
        if (gid < n * 32) zero_agg[gid] = 0.f;
        if (gid < n)      zero_den[gid] = 0.f;
    }

    int group = gid >> 3;
    int lane  = threadIdx.x & 7;
    int ebase = group * 4;
    if (ebase >= ne) return;
    unsigned mask = __activemask();

    int s[4], d[4];
    #pragma unroll
    for (int k = 0; k < 4; k++) {
        int e = ebase + k;
        bool ok = (e < ne);
        s[k] = ok ? src[e] : src[ebase];
        d[k] = ok ? dst[e] : dst[ebase];
    }

    uint2 pa[4], pb[4];
    #pragma unroll
    for (int k = 0; k < 4; k++) {
        pa[k] = *(reinterpret_cast<const uint2*>(hn + (size_t)s[k] * 32) + lane);
        pb[k] = *(reinterpret_cast<const uint2*>(hn + (size_t)d[k] * 32) + lane);
    }

    float beta = __ldg(&betas[layer]);
    float p[4];
    #pragma unroll
    for (int k = 0; k < 4; k++) {
        __half2 A0 = *reinterpret_cast<const __half2*>(&pa[k].x);
        __half2 A1 = *reinterpret_cast<const __half2*>(&pa[k].y);
        __half2 B0 = *reinterpret_cast<const __half2*>(&pb[k].x);
        __half2 B1 = *reinterpret_cast<const __half2*>(&pb[k].y);
        __half2 ph = __hfma2(A0, B0, __hmul2(A1, B1));
        float2 pf = __half22float2(ph);
        p[k] = pf.x + pf.y;
    }
    #pragma unroll
    for (int k = 0; k < 4; k++) p[k] += __shfl_xor_sync(mask, p[k], 1);
    #pragma unroll
    for (int k = 0; k < 4; k++) p[k] += __shfl_xor_sync(mask, p[k], 2);
    #pragma unroll
    for (int k = 0; k < 4; k++) p[k] += __shfl_xor_sync(mask, p[k], 4);

    #pragma unroll
    for (int k = 0; k < 4; k++) {
        if (ebase + k >= ne) break;
        float v = __expf(beta * p[k]);
        float w = v * __ldg(&normv[s[k]]);
        float2 a0 = __half22float2(*reinterpret_cast<const __half2*>(&pa[k].x));
        float2 a1 = __half22float2(*reinterpret_cast<const __half2*>(&pa[k].y));
        if (lane == 0) atomicAdd(&denom[d[k]], v);
        atomicAdd(reinterpret_cast<float4*>(agg + (size_t)d[k] * 32) + lane,
                  make_float4(w * a0.x, w * a0.y, w * a1.x, w * a1.y));
    }
}

// ---------------------------------------------------------------------------
// Layer-0 node pass (R13 exact).
__global__ __launch_bounds__(256) void k_norm_mid(
    const float* __restrict__ agg, const float* __restrict__ denom,
    __half* __restrict__ hn, float* __restrict__ normv, int n)
{
    int gid  = blockIdx.x * 256 + threadIdx.x;
    int node = gid >> 3;
    int lane = threadIdx.x & 7;
    if (node >= n) return;
    unsigned mask = __activemask();

    float4 v = *(reinterpret_cast<const float4*>(agg + (size_t)node * 32) + lane);
    v.x = fmaxf(v.x, 0.f); v.y = fmaxf(v.y, 0.f);
    v.z = fmaxf(v.z, 0.f); v.w = fmaxf(v.w, 0.f);

    float ss = v.x * v.x + v.y * v.y + v.z * v.z + v.w * v.w;
    ss += __shfl_xor_sync(mask, ss, 1);
    ss += __shfl_xor_sync(mask, ss, 2);
    ss += __shfl_xor_sync(mask, ss, 4);

    float nv = fmaxf(sqrtf(ss), EPSF);
    float rinv = 1.0f / nv;
    if (lane == 0) {
        float inv = 1.0f / fmaxf(denom[node], EPSF);
        normv[node] = nv * inv;
    }

    __half2 h0 = __floats2half2_rn(v.x * rinv, v.y * rinv);
    __half2 h1 = __floats2half2_rn(v.z * rinv, v.w * rinv);
    uint2 pk;
    pk.x = *reinterpret_cast<unsigned*>(&h0);
    pk.y = *reinterpret_cast<unsigned*>(&h1);
    *(reinterpret_cast<uint2*>(hn + (size_t)node * 32) + lane) = pk;
}

// ---------------------------------------------------------------------------
// Head, pair-blocked (R13 exact).
__global__ __launch_bounds__(256) void k_final(
    const float* __restrict__ agg, const float* __restrict__ denom,
    const float* __restrict__ w2, const float* __restrict__ b2,
    float* __restrict__ out, int n)
{
    __shared__ float w2t[32 * 64];
    __shared__ float b2s[64];
    for (int i = threadIdx.x; i < 2048; i += 256) {
        int j = i >> 5, k = i & 31;
        w2t[k * 64 + j] = w2[i];
    }
    for (int i = threadIdx.x; i < 64; i += 256) b2s[i] = b2[i];
    __syncthreads();

    int gid  = blockIdx.x * 256 + threadIdx.x;
    int pair = gid >> 1;
    int jh   = gid & 1;
    int n0   = pair * 2;
    int n1   = n0 + 1;
    if (n0 >= n) return;
    bool has1 = (n1 < n);

    float inv0 = 1.0f / fmaxf(denom[n0], EPSF);
    float inv1 = has1 ? (1.0f / fmaxf(denom[n1], EPSF)) : 0.f;

    float acc0[32], acc1[32];
    #pragma unroll
    for (int j = 0; j < 32; j++) {
        float b = b2s[jh * 32 + j];
        acc0[j] = b; acc1[j] = b;
    }

    const float4* h0 = reinterpret_cast<const float4*>(agg + (size_t)n0 * 32);
    const float4* h1 = reinterpret_cast<const float4*>(agg + (size_t)(has1 ? n1 : n0) * 32);

    #pragma unroll
    for (int k4 = 0; k4 < 8; k4++) {
        float4 hv0 = h0[k4];
        float4 hv1 = h1[k4];
        float hh0[4] = {fmaxf(hv0.x*inv0,0.f), fmaxf(hv0.y*inv0,0.f),
                        fmaxf(hv0.z*inv0,0.f), fmaxf(hv0.w*inv0,0.f)};
        float hh1[4] = {fmaxf(hv1.x*inv1,0.f), fmaxf(hv1.y*inv1,0.f),
                        fmaxf(hv1.z*inv1,0.f), fmaxf(hv1.w*inv1,0.f)};
        #pragma unroll
        for (int c = 0; c < 4; c++) {
            const float4* w4 = reinterpret_cast<const float4*>(
                &w2t[(k4 * 4 + c) * 64 + jh * 32]);
            float f0 = hh0[c], f1 = hh1[c];
            #pragma unroll
            for (int j4 = 0; j4 < 8; j4++) {
                float4 w = w4[j4];
                acc0[j4*4+0] += f0*w.x; acc0[j4*4+1] += f0*w.y;
                acc0[j4*4+2] += f0*w.z; acc0[j4*4+3] += f0*w.w;
                acc1[j4*4+0] += f1*w.x; acc1[j4*4+1] += f1*w.y;
                acc1[j4*4+2] += f1*w.z; acc1[j4*4+3] += f1*w.w;
            }
        }
    }

    float mx0 = acc0[0], mx1 = acc1[0];
    #pragma unroll
    for (int j = 1; j < 32; j++) { mx0 = fmaxf(mx0, acc0[j]); mx1 = fmaxf(mx1, acc1[j]); }
    mx0 = fmaxf(mx0, __shfl_xor_sync(FULLM, mx0, 1));
    mx1 = fmaxf(mx1, __shfl_xor_sync(FULLM, mx1, 1));

    float sum0 = 0.f, sum1 = 0.f;
    #pragma unroll
    for (int j = 0; j < 32; j++) {
        sum0 += __expf(acc0[j] - mx0);
        sum1 += __expf(acc1[j] - mx1);
    }
    sum0 += __shfl_xor_sync(FULLM, sum0, 1);
    sum1 += __shfl_xor_sync(FULLM, sum1, 1);

    float lse0 = mx0 + __logf(sum0);
    float lse1 = mx1 + __logf(sum1);

    float4* o0 = reinterpret_cast<float4*>(out + (size_t)n0 * 64 + jh * 32);
    #pragma unroll
    for (int j4 = 0; j4 < 8; j4++)
        o0[j4] = make_float4(acc0[j4*4]-lse0, acc0[j4*4+1]-lse0,
                             acc0[j4*4+2]-lse0, acc0[j4*4+3]-lse0);
    if (has1) {
        float4* o1 = reinterpret_cast<float4*>(out + (size_t)n1 * 64 + jh * 32);
        #pragma unroll
        for (int j4 = 0; j4 < 8; j4++)
            o1[j4] = make_float4(acc1[j4*4]-lse1, acc1[j4*4+1]-lse1,
                                 acc1[j4*4+2]-lse1, acc1[j4*4+3]-lse1);
    }
}

// ---------------------------------------------------------------------------
extern "C" void kernel_launch(void* const* d_in, const int* in_sizes, int n_in,
                              void* d_out, int out_size)
{
    const float* feat  = (const float*)d_in[0];
    const int*   src   = (const int*)d_in[1];
    const int*   dst   = (const int*)d_in[2];
    const float* w1    = (const float*)d_in[3];
    const float* b1    = (const float*)d_in[4];
    const float* betas = (const float*)d_in[5];
    const float* w2    = (const float*)d_in[6];
    const float* b2    = (const float*)d_in[7];
    float*       out   = (float*)d_out;

    const int n  = in_sizes[0] / 128;   // 100000
    const int ne = in_sizes[1];         // 1600000

    float *aggA, *aggB, *normv, *denA, *denB;
    __half *hnA, *hnB;
    cudaGetSymbolAddress((void**)&aggA,  g_aggA);
    cudaGetSymbolAddress((void**)&aggB,  g_aggB);
    cudaGetSymbolAddress((void**)&hnA,   g_hnA);
    cudaGetSymbolAddress((void**)&hnB,   g_hnB);
    cudaGetSymbolAddress((void**)&normv, g_norm);
    cudaGetSymbolAddress((void**)&denA,  g_denomA);
    cudaGetSymbolAddress((void**)&denB,  g_denomB);

    const int TB = 256;
    const int n_agg4 = n * 32 / 4;
    const int n_den4 = n / 4;
    const int ngroups = (ne + 3) / 4;
    dim3 gN((n + TB - 1) / TB);
    dim3 gN8(((size_t)n * 8 + TB - 1) / TB);
    dim3 gG8(((size_t)ngroups * 8 + TB - 1) / TB);
    dim3 gZ((n_agg4 + TB - 1) / TB);

    // Zero layer-0 accumulators only (layer-1 zeroed inside edge-0 prologue).
    k_zero_A<<<gZ, TB>>>((float4*)aggA, (float4*)denA, n_agg4, n_den4);

    // K1: hn0/norm0 (pair-blocked)
    k_gemm1<<<gN, TB>>>(feat, w1, b1, hnA, normv, n);

    // ---- layer 0: hnA -> aggA/denA -> hnB ; also zeroes aggB/denB ----
    k_edge_fused<<<gG8, TB>>>(src, dst, hnA, normv, betas, 0, denA, aggA,
                              aggB, denB, n, ne);
    k_norm_mid<<<gN8, TB>>>(aggA, denA, hnB, normv, n);

    // ---- layer 1: hnB -> aggB/denB ----
    k_edge_fused<<<gG8, TB>>>(src, dst, hnB, normv, betas, 1, denB, aggB,
                              (float*)nullptr, (float*)nullptr, n, ne);

    // Head (pair-blocked)
    k_final<<<gN, TB>>>(aggB, denB, w2, b2, out, n);
}

// round 15
// speedup vs baseline: 1.0107x; 1.0107x over previous
#include <cuda_runtime.h>
#include <cuda_fp16.h>
#include <math.h>

// ---------------------------------------------------------------------------
// AGNN — fp16 normalized features; pair-blocked gemm1/final; NO zero kernel:
// edge-0 prologue zeroes layer-1 accumulators, edge-1 prologue re-zeroes
// layer-0 accumulators for the next invocation (device globals start zeroed,
// so the invariant "agg/den zero at their producer's start" is self-
// maintaining across graph replays).
// ---------------------------------------------------------------------------

#define NN 100000
#define NE 1600000
#define EPSF 1e-12f
#define FULLM 0xFFFFFFFFu

__device__ __align__(128) float  g_aggA[NN * 32];   // zero-init at load
__device__ __align__(128) float  g_aggB[NN * 32];
__device__ __align__(128) __half g_hnA[NN * 32];
__device__ __align__(128) __half g_hnB[NN * 32];
__device__ __align__(128) float  g_norm[NN];
__device__ __align__(128) float  g_denomA[NN];
__device__ __align__(128) float  g_denomB[NN];

// ---------------------------------------------------------------------------
// GEMM1, pair-blocked: threads (t, t^1) handle nodes (2p, 2p+1).
__global__ __launch_bounds__(256) void k_gemm1(
    const float* __restrict__ feat, const float* __restrict__ w1,
    const float* __restrict__ b1, __half* __restrict__ hn,
    float* __restrict__ normv, int n)
{
    __shared__ float w1t[128 * 32];   // [k][j]
    __shared__ float b1s[32];
    for (int i = threadIdx.x; i < 4096; i += 256) {
        int j = i >> 7, k = i & 127;
        w1t[k * 32 + j] = w1[i];
    }
    if (threadIdx.x < 32) b1s[threadIdx.x] = b1[threadIdx.x];
    __syncthreads();

    int gid  = blockIdx.x * 256 + threadIdx.x;
    int pair = gid >> 1;
    int jh   = gid & 1;
    int n0   = pair * 2;
    int n1   = n0 + 1;
    if (n0 >= n) return;
    bool has1 = (n1 < n);

    float acc0[16], acc1[16];
    #pragma unroll
    for (int j = 0; j < 16; j++) {
        float b = b1s[jh * 16 + j];
        acc0[j] = b; acc1[j] = b;
    }

    const float4* f0 = reinterpret_cast<const float4*>(feat + (size_t)n0 * 128);
    const float4* f1 = reinterpret_cast<const float4*>(feat + (size_t)(has1 ? n1 : n0) * 128);

    #pragma unroll 4
    for (int k4 = 0; k4 < 32; k4++) {
        float4 fa = f0[k4];
        float4 fb = f1[k4];
        float fv0[4] = {fa.x, fa.y, fa.z, fa.w};
        float fv1[4] = {fb.x, fb.y, fb.z, fb.w};
        #pragma unroll
        for (int c = 0; c < 4; c++) {
            const float4* w4 = reinterpret_cast<const float4*>(
                &w1t[(k4 * 4 + c) * 32 + jh * 16]);
            #pragma unroll
            for (int j4 = 0; j4 < 4; j4++) {
                float4 w = w4[j4];
                acc0[j4*4+0] += fv0[c]*w.x; acc0[j4*4+1] += fv0[c]*w.y;
                acc0[j4*4+2] += fv0[c]*w.z; acc0[j4*4+3] += fv0[c]*w.w;
                acc1[j4*4+0] += fv1[c]*w.x; acc1[j4*4+1] += fv1[c]*w.y;
                acc1[j4*4+2] += fv1[c]*w.z; acc1[j4*4+3] += fv1[c]*w.w;
            }
        }
    }

    float ss0 = 0.f, ss1 = 0.f;
    #pragma unroll
    for (int j = 0; j < 16; j++) {
        float v0 = fmaxf(acc0[j], 0.f); acc0[j] = v0; ss0 += v0 * v0;
        float v1 = fmaxf(acc1[j], 0.f); acc1[j] = v1; ss1 += v1 * v1;
    }
    ss0 += __shfl_xor_sync(FULLM, ss0, 1);
    ss1 += __shfl_xor_sync(FULLM, ss1, 1);

    float nv0 = fmaxf(sqrtf(ss0), EPSF), rinv0 = 1.0f / nv0;
    float nv1 = fmaxf(sqrtf(ss1), EPSF), rinv1 = 1.0f / nv1;
    if (jh == 0) {
        normv[n0] = nv0;
        if (has1) normv[n1] = nv1;
    }

    __half2 hp0[8], hp1[8];
    #pragma unroll
    for (int j = 0; j < 8; j++) {
        hp0[j] = __floats2half2_rn(acc0[2*j] * rinv0, acc0[2*j+1] * rinv0);
        hp1[j] = __floats2half2_rn(acc1[2*j] * rinv1, acc1[2*j+1] * rinv1);
    }
    uint4* o0 = reinterpret_cast<uint4*>(hn + (size_t)n0 * 32 + jh * 16);
    o0[0] = reinterpret_cast<const uint4*>(hp0)[0];
    o0[1] = reinterpret_cast<const uint4*>(hp0)[1];
    if (has1) {
        uint4* o1 = reinterpret_cast<uint4*>(hn + (size_t)n1 * 32 + jh * 16);
        o1[0] = reinterpret_cast<const uint4*>(hp1)[0];
        o1[1] = reinterpret_cast<const uint4*>(hp1)[1];
    }
}

// ---------------------------------------------------------------------------
// Fused edge pass: 8 lanes/edge, 4 edges/group, HFMA2 dot.
// Prologue: each thread zeroes one float of zero_agg (+ first n threads zero
// zero_den) — the OPPOSITE layer's accumulators, which are not live here.
__global__ __launch_bounds__(256) void k_edge_fused(
    const int* __restrict__ src, const int* __restrict__ dst,
    const __half* __restrict__ hn, const float* __restrict__ normv,
    const float* __restrict__ betas, int layer,
    float* __restrict__ denom, float* __restrict__ agg,
    float* __restrict__ zero_agg, float* __restrict__ zero_den,
    int n, int ne)
{
    int gid = blockIdx.x * 256 + threadIdx.x;

    if (gid < n * 32) zero_agg[gid] = 0.f;
    if (gid < n)      zero_den[gid] = 0.f;

    int group = gid >> 3;
    int lane  = threadIdx.x & 7;
    int ebase = group * 4;
    if (ebase >= ne) return;
    unsigned mask = __activemask();

    int s[4], d[4];
    #pragma unroll
    for (int k = 0; k < 4; k++) {
        int e = ebase + k;
        bool ok = (e < ne);
        s[k] = ok ? src[e] : src[ebase];
        d[k] = ok ? dst[e] : dst[ebase];
    }

    uint2 pa[4], pb[4];
    #pragma unroll
    for (int k = 0; k < 4; k++) {
        pa[k] = *(reinterpret_cast<const uint2*>(hn + (size_t)s[k] * 32) + lane);
        pb[k] = *(reinterpret_cast<const uint2*>(hn + (size_t)d[k] * 32) + lane);
    }

    float beta = __ldg(&betas[layer]);
    float p[4];
    #pragma unroll
    for (int k = 0; k < 4; k++) {
        __half2 A0 = *reinterpret_cast<const __half2*>(&pa[k].x);
        __half2 A1 = *reinterpret_cast<const __half2*>(&pa[k].y);
        __half2 B0 = *reinterpret_cast<const __half2*>(&pb[k].x);
        __half2 B1 = *reinterpret_cast<const __half2*>(&pb[k].y);
        __half2 ph = __hfma2(A0, B0, __hmul2(A1, B1));
        float2 pf = __half22float2(ph);
        p[k] = pf.x + pf.y;
    }
    #pragma unroll
    for (int k = 0; k < 4; k++) p[k] += __shfl_xor_sync(mask, p[k], 1);
    #pragma unroll
    for (int k = 0; k < 4; k++) p[k] += __shfl_xor_sync(mask, p[k], 2);
    #pragma unroll
    for (int k = 0; k < 4; k++) p[k] += __shfl_xor_sync(mask, p[k], 4);

    #pragma unroll
    for (int k = 0; k < 4; k++) {
        if (ebase + k >= ne) break;
        float v = __expf(beta * p[k]);
        float w = v * __ldg(&normv[s[k]]);
        float2 a0 = __half22float2(*reinterpret_cast<const __half2*>(&pa[k].x));
        float2 a1 = __half22float2(*reinterpret_cast<const __half2*>(&pa[k].y));
        if (lane == 0) atomicAdd(&denom[d[k]], v);
        atomicAdd(reinterpret_cast<float4*>(agg + (size_t)d[k] * 32) + lane,
                  make_float4(w * a0.x, w * a0.y, w * a1.x, w * a1.y));
    }
}

// ---------------------------------------------------------------------------
// Layer-0 node pass, 8 lanes/node:
//   hn' = relu(agg)/||relu(agg)||, norm' = ||relu(agg)||/denom.
__global__ __launch_bounds__(256) void k_norm_mid(
    const float* __restrict__ agg, const float* __restrict__ denom,
    __half* __restrict__ hn, float* __restrict__ normv, int n)
{
    int gid  = blockIdx.x * 256 + threadIdx.x;
    int node = gid >> 3;
    int lane = threadIdx.x & 7;
    if (node >= n) return;
    unsigned mask = __activemask();

    float4 v = *(reinterpret_cast<const float4*>(agg + (size_t)node * 32) + lane);
    v.x = fmaxf(v.x, 0.f); v.y = fmaxf(v.y, 0.f);
    v.z = fmaxf(v.z, 0.f); v.w = fmaxf(v.w, 0.f);

    float ss = v.x * v.x + v.y * v.y + v.z * v.z + v.w * v.w;
    ss += __shfl_xor_sync(mask, ss, 1);
    ss += __shfl_xor_sync(mask, ss, 2);
    ss += __shfl_xor_sync(mask, ss, 4);

    float nv = fmaxf(sqrtf(ss), EPSF);
    float rinv = 1.0f / nv;
    if (lane == 0) {
        float inv = 1.0f / fmaxf(denom[node], EPSF);
        normv[node] = nv * inv;
    }

    __half2 h0 = __floats2half2_rn(v.x * rinv, v.y * rinv);
    __half2 h1 = __floats2half2_rn(v.z * rinv, v.w * rinv);
    uint2 pk;
    pk.x = *reinterpret_cast<unsigned*>(&h0);
    pk.y = *reinterpret_cast<unsigned*>(&h1);
    *(reinterpret_cast<uint2*>(hn + (size_t)node * 32) + lane) = pk;
}

// ---------------------------------------------------------------------------
// Head, pair-blocked: threads (t, t^1) handle nodes (2p, 2p+1).
__global__ __launch_bounds__(256) void k_final(
    const float* __restrict__ agg, const float* __restrict__ denom,
    const float* __restrict__ w2, const float* __restrict__ b2,
    float* __restrict__ out, int n)
{
    __shared__ float w2t[32 * 64];
    __shared__ float b2s[64];
    for (int i = threadIdx.x; i < 2048; i += 256) {
        int j = i >> 5, k = i & 31;
        w2t[k * 64 + j] = w2[i];
    }
    for (int i = threadIdx.x; i < 64; i += 256) b2s[i] = b2[i];
    __syncthreads();

    int gid  = blockIdx.x * 256 + threadIdx.x;
    int pair = gid >> 1;
    int jh   = gid & 1;
    int n0   = pair * 2;
    int n1   = n0 + 1;
    if (n0 >= n) return;
    bool has1 = (n1 < n);

    float inv0 = 1.0f / fmaxf(denom[n0], EPSF);
    float inv1 = has1 ? (1.0f / fmaxf(denom[n1], EPSF)) : 0.f;

    float acc0[32], acc1[32];
    #pragma unroll
    for (int j = 0; j < 32; j++) {
        float b = b2s[jh * 32 + j];
        acc0[j] = b; acc1[j] = b;
    }

    const float4* h0 = reinterpret_cast<const float4*>(agg + (size_t)n0 * 32);
    const float4* h1 = reinterpret_cast<const float4*>(agg + (size_t)(has1 ? n1 : n0) * 32);

    #pragma unroll
    for (int k4 = 0; k4 < 8; k4++) {
        float4 hv0 = h0[k4];
        float4 hv1 = h1[k4];
        float hh0[4] = {fmaxf(hv0.x*inv0,0.f), fmaxf(hv0.y*inv0,0.f),
                        fmaxf(hv0.z*inv0,0.f), fmaxf(hv0.w*inv0,0.f)};
        float hh1[4] = {fmaxf(hv1.x*inv1,0.f), fmaxf(hv1.y*inv1,0.f),
                        fmaxf(hv1.z*inv1,0.f), fmaxf(hv1.w*inv1,0.f)};
        #pragma unroll
        for (int c = 0; c < 4; c++) {
            const float4* w4 = reinterpret_cast<const float4*>(
                &w2t[(k4 * 4 + c) * 64 + jh * 32]);
            float f0 = hh0[c], f1 = hh1[c];
            #pragma unroll
            for (int j4 = 0; j4 < 8; j4++) {
                float4 w = w4[j4];
                acc0[j4*4+0] += f0*w.x; acc0[j4*4+1] += f0*w.y;
                acc0[j4*4+2] += f0*w.z; acc0[j4*4+3] += f0*w.w;
                acc1[j4*4+0] += f1*w.x; acc1[j4*4+1] += f1*w.y;
                acc1[j4*4+2] += f1*w.z; acc1[j4*4+3] += f1*w.w;
            }
        }
    }

    float mx0 = acc0[0], mx1 = acc1[0];
    #pragma unroll
    for (int j = 1; j < 32; j++) { mx0 = fmaxf(mx0, acc0[j]); mx1 = fmaxf(mx1, acc1[j]); }
    mx0 = fmaxf(mx0, __shfl_xor_sync(FULLM, mx0, 1));
    mx1 = fmaxf(mx1, __shfl_xor_sync(FULLM, mx1, 1));

    float sum0 = 0.f, sum1 = 0.f;
    #pragma unroll
    for (int j = 0; j < 32; j++) {
        sum0 += __expf(acc0[j] - mx0);
        sum1 += __expf(acc1[j] - mx1);
    }
    sum0 += __shfl_xor_sync(FULLM, sum0, 1);
    sum1 += __shfl_xor_sync(FULLM, sum1, 1);

    float lse0 = mx0 + __logf(sum0);
    float lse1 = mx1 + __logf(sum1);

    float4* o0 = reinterpret_cast<float4*>(out + (size_t)n0 * 64 + jh * 32);
    #pragma unroll
    for (int j4 = 0; j4 < 8; j4++)
        o0[j4] = make_float4(acc0[j4*4]-lse0, acc0[j4*4+1]-lse0,
                             acc0[j4*4+2]-lse0, acc0[j4*4+3]-lse0);
    if (has1) {
        float4* o1 = reinterpret_cast<float4*>(out + (size_t)n1 * 64 + jh * 32);
        #pragma unroll
        for (int j4 = 0; j4 < 8; j4++)
            o1[j4] = make_float4(acc1[j4*4]-lse1, acc1[j4*4+1]-lse1,
                                 acc1[j4*4+2]-lse1, acc1[j4*4+3]-lse1);
    }
}

// ---------------------------------------------------------------------------
extern "C" void kernel_launch(void* const* d_in, const int* in_sizes, int n_in,
                              void* d_out, int out_size)
{
    const float* feat  = (const float*)d_in[0];
    const int*   src   = (const int*)d_in[1];
    const int*   dst   = (const int*)d_in[2];
    const float* w1    = (const float*)d_in[3];
    const float* b1    = (const float*)d_in[4];
    const float* betas = (const float*)d_in[5];
    const float* w2    = (const float*)d_in[6];
    const float* b2    = (const float*)d_in[7];
    float*       out   = (float*)d_out;

    const int n  = in_sizes[0] / 128;   // 100000
    const int ne = in_sizes[1];         // 1600000

    float *aggA, *aggB, *normv, *denA, *denB;
    __half *hnA, *hnB;
    cudaGetSymbolAddress((void**)&aggA,  g_aggA);
    cudaGetSymbolAddress((void**)&aggB,  g_aggB);
    cudaGetSymbolAddress((void**)&hnA,   g_hnA);
    cudaGetSymbolAddress((void**)&hnB,   g_hnB);
    cudaGetSymbolAddress((void**)&normv, g_norm);
    cudaGetSymbolAddress((void**)&denA,  g_denomA);
    cudaGetSymbolAddress((void**)&denB,  g_denomB);

    const int TB = 256;
    const int ngroups = (ne + 3) / 4;
    dim3 gN((n + TB - 1) / TB);
    dim3 gN8(((size_t)n * 8 + TB - 1) / TB);
    dim3 gG8(((size_t)ngroups * 8 + TB - 1) / TB);

    // Invariant: aggA/denA zero here (zero-init at load; re-zeroed by edge-1
    // prologue each invocation). aggB/denB zeroed by edge-0 prologue below.

    // K1: hn0/norm0 (pair-blocked)
    k_gemm1<<<gN, TB>>>(feat, w1, b1, hnA, normv, n);

    // ---- layer 0: hnA -> aggA/denA ; prologue zeroes aggB/denB ----
    k_edge_fused<<<gG8, TB>>>(src, dst, hnA, normv, betas, 0, denA, aggA,
                              aggB, denB, n, ne);
    k_norm_mid<<<gN8, TB>>>(aggA, denA, hnB, normv, n);

    // ---- layer 1: hnB -> aggB/denB ; prologue re-zeroes aggA/denA ----
    k_edge_fused<<<gG8, TB>>>(src, dst, hnB, normv, betas, 1, denB, aggB,
                              aggA, denA, n, ne);

    // Head (pair-blocked)
    k_final<<<gN, TB>>>(aggB, denB, w2, b2, out, n);
}

// round 17
// speedup vs baseline: 1.0324x; 1.0215x over previous
#include <cuda_runtime.h>
#include <cuda_fp16.h>
#include <math.h>

// ---------------------------------------------------------------------------
// AGNN — fp16 normalized features; pair-blocked gemm1 (HFMA2, chunked fp16
// accumulation) and final; no zero kernel (cyclic prologue zeroing).
// ---------------------------------------------------------------------------

#define NN 100000
#define NE 1600000
#define EPSF 1e-12f
#define FULLM 0xFFFFFFFFu

__device__ __align__(128) float  g_aggA[NN * 32];   // zero-init at load
__device__ __align__(128) float  g_aggB[NN * 32];
__device__ __align__(128) __half g_hnA[NN * 32];
__device__ __align__(128) __half g_hnB[NN * 32];
__device__ __align__(128) float  g_norm[NN];
__device__ __align__(128) float  g_denomA[NN];
__device__ __align__(128) float  g_denomB[NN];

// ---------------------------------------------------------------------------
// GEMM1, pair-blocked, HFMA2: threads (t, t^1) handle nodes (2p, 2p+1);
// each thread computes 16 of 32 outputs for both nodes.
// k accumulated in fp16 within 4 chunks of 32 k, fp32 across chunks.
__global__ __launch_bounds__(256) void k_gemm1(
    const float* __restrict__ feat, const float* __restrict__ w1,
    const float* __restrict__ b1, __half* __restrict__ hn,
    float* __restrict__ normv, int n)
{
    __shared__ __half2 w1h[64 * 32];   // [kp][j] = (w1[j][2kp], w1[j][2kp+1])
    __shared__ float b1s[32];
    for (int i = threadIdx.x; i < 2048; i += 256) {
        int kp = i >> 5, j = i & 31;
        float2 f2 = *reinterpret_cast<const float2*>(w1 + j * 128 + kp * 2);
        w1h[kp * 32 + j] = __floats2half2_rn(f2.x, f2.y);
    }
    if (threadIdx.x < 32) b1s[threadIdx.x] = b1[threadIdx.x];
    __syncthreads();

    int gid  = blockIdx.x * 256 + threadIdx.x;
    int pair = gid >> 1;
    int jh   = gid & 1;
    int n0   = pair * 2;
    int n1   = n0 + 1;
    if (n0 >= n) return;
    bool has1 = (n1 < n);

    float accf0[16], accf1[16];
    #pragma unroll
    for (int j = 0; j < 16; j++) {
        float b = b1s[jh * 16 + j];
        accf0[j] = b; accf1[j] = b;
    }

    const float4* f0p = reinterpret_cast<const float4*>(feat + (size_t)n0 * 128);
    const float4* f1p = reinterpret_cast<const float4*>(feat + (size_t)(has1 ? n1 : n0) * 128);
    const __half2 hz = __floats2half2_rn(0.f, 0.f);

    #pragma unroll
    for (int ch = 0; ch < 4; ch++) {
        __half2 acch0[16], acch1[16];
        #pragma unroll
        for (int j = 0; j < 16; j++) { acch0[j] = hz; acch1[j] = hz; }

        #pragma unroll
        for (int q = 0; q < 8; q++) {          // 8 float4 = 16 kpairs per chunk
            int k4 = ch * 8 + q;
            float4 fa = f0p[k4];
            float4 fb = f1p[k4];
            __half2 fa01 = __floats2half2_rn(fa.x, fa.y);
            __half2 fa23 = __floats2half2_rn(fa.z, fa.w);
            __half2 fb01 = __floats2half2_rn(fb.x, fb.y);
            __half2 fb23 = __floats2half2_rn(fb.z, fb.w);

            const uint4* wr0 = reinterpret_cast<const uint4*>(
                &w1h[(k4 * 2 + 0) * 32 + jh * 16]);
            const uint4* wr1 = reinterpret_cast<const uint4*>(
                &w1h[(k4 * 2 + 1) * 32 + jh * 16]);
            #pragma unroll
            for (int v = 0; v < 4; v++) {
                uint4 wa = wr0[v];
                uint4 wb = wr1[v];
                const __half2* wah = reinterpret_cast<const __half2*>(&wa);
                const __half2* wbh = reinterpret_cast<const __half2*>(&wb);
                #pragma unroll
                for (int e = 0; e < 4; e++) {
                    int j = v * 4 + e;
                    acch0[j] = __hfma2(fa01, wah[e], acch0[j]);
                    acch1[j] = __hfma2(fb01, wah[e], acch1[j]);
                    acch0[j] = __hfma2(fa23, wbh[e], acch0[j]);
                    acch1[j] = __hfma2(fb23, wbh[e], acch1[j]);
                }
            }
        }

        #pragma unroll
        for (int j = 0; j < 16; j++) {
            float2 t0 = __half22float2(acch0[j]);
            float2 t1 = __half22float2(acch1[j]);
            accf0[j] += t0.x + t0.y;
            accf1[j] += t1.x + t1.y;
        }
    }

    float ss0 = 0.f, ss1 = 0.f;
    #pragma unroll
    for (int j = 0; j < 16; j++) {
        float v0 = fmaxf(accf0[j], 0.f); accf0[j] = v0; ss0 += v0 * v0;
        float v1 = fmaxf(accf1[j], 0.f); accf1[j] = v1; ss1 += v1 * v1;
    }
    ss0 += __shfl_xor_sync(FULLM, ss0, 1);
    ss1 += __shfl_xor_sync(FULLM, ss1, 1);

    float nv0 = fmaxf(sqrtf(ss0), EPSF), rinv0 = 1.0f / nv0;
    float nv1 = fmaxf(sqrtf(ss1), EPSF), rinv1 = 1.0f / nv1;
    if (jh == 0) {
        normv[n0] = nv0;
        if (has1) normv[n1] = nv1;
    }

    __half2 hp0[8], hp1[8];
    #pragma unroll
    for (int j = 0; j < 8; j++) {
        hp0[j] = __floats2half2_rn(accf0[2*j] * rinv0, accf0[2*j+1] * rinv0);
        hp1[j] = __floats2half2_rn(accf1[2*j] * rinv1, accf1[2*j+1] * rinv1);
    }
    uint4* o0 = reinterpret_cast<uint4*>(hn + (size_t)n0 * 32 + jh * 16);
    o0[0] = reinterpret_cast<const uint4*>(hp0)[0];
    o0[1] = reinterpret_cast<const uint4*>(hp0)[1];
    if (has1) {
        uint4* o1 = reinterpret_cast<uint4*>(hn + (size_t)n1 * 32 + jh * 16);
        o1[0] = reinterpret_cast<const uint4*>(hp1)[0];
        o1[1] = reinterpret_cast<const uint4*>(hp1)[1];
    }
}

// ---------------------------------------------------------------------------
// Fused edge pass: 8 lanes/edge, 4 edges/group, HFMA2 dot.
// Prologue zeroes the OPPOSITE layer's accumulators (1 float/thread).
__global__ __launch_bounds__(256) void k_edge_fused(
    const int* __restrict__ src, const int* __restrict__ dst,
    const __half* __restrict__ hn, const float* __restrict__ normv,
    const float* __restrict__ betas, int layer,
    float* __restrict__ denom, float* __restrict__ agg,
    float* __restrict__ zero_agg, float* __restrict__ zero_den,
    int n, int ne)
{
    int gid = blockIdx.x * 256 + threadIdx.x;

    if (gid < n * 32) zero_agg[gid] = 0.f;
    if (gid < n)      zero_den[gid] = 0.f;

    int group = gid >> 3;
    int lane  = threadIdx.x & 7;
    int ebase = group * 4;
    if (ebase >= ne) return;
    unsigned mask = __activemask();

    int s[4], d[4];
    #pragma unroll
    for (int k = 0; k < 4; k++) {
        int e = ebase + k;
        bool ok = (e < ne);
        s[k] = ok ? src[e] : src[ebase];
        d[k] = ok ? dst[e] : dst[ebase];
    }

    uint2 pa[4], pb[4];
    #pragma unroll
    for (int k = 0; k < 4; k++) {
        pa[k] = *(reinterpret_cast<const uint2*>(hn + (size_t)s[k] * 32) + lane);
        pb[k] = *(reinterpret_cast<const uint2*>(hn + (size_t)d[k] * 32) + lane);
    }

    float beta = __ldg(&betas[layer]);
    float p[4];
    #pragma unroll
    for (int k = 0; k < 4; k++) {
        __half2 A0 = *reinterpret_cast<const __half2*>(&pa[k].x);
        __half2 A1 = *reinterpret_cast<const __half2*>(&pa[k].y);
        __half2 B0 = *reinterpret_cast<const __half2*>(&pb[k].x);
        __half2 B1 = *reinterpret_cast<const __half2*>(&pb[k].y);
        __half2 ph = __hfma2(A0, B0, __hmul2(A1, B1));
        float2 pf = __half22float2(ph);
        p[k] = pf.x + pf.y;
    }
    #pragma unroll
    for (int k = 0; k < 4; k++) p[k] += __shfl_xor_sync(mask, p[k], 1);
    #pragma unroll
    for (int k = 0; k < 4; k++) p[k] += __shfl_xor_sync(mask, p[k], 2);
    #pragma unroll
    for (int k = 0; k < 4; k++) p[k] += __shfl_xor_sync(mask, p[k], 4);

    #pragma unroll
    for (int k = 0; k < 4; k++) {
        if (ebase + k >= ne) break;
        float v = __expf(beta * p[k]);
        float w = v * __ldg(&normv[s[k]]);
        float2 a0 = __half22float2(*reinterpret_cast<const __half2*>(&pa[k].x));
        float2 a1 = __half22float2(*reinterpret_cast<const __half2*>(&pa[k].y));
        if (lane == 0) atomicAdd(&denom[d[k]], v);
        atomicAdd(reinterpret_cast<float4*>(agg + (size_t)d[k] * 32) + lane,
                  make_float4(w * a0.x, w * a0.y, w * a1.x, w * a1.y));
    }
}

// ---------------------------------------------------------------------------
// Layer-0 node pass, 8 lanes/node:
//   hn' = relu(agg)/||relu(agg)||, norm' = ||relu(agg)||/denom.
__global__ __launch_bounds__(256) void k_norm_mid(
    const float* __restrict__ agg, const float* __restrict__ denom,
    __half* __restrict__ hn, float* __restrict__ normv, int n)
{
    int gid  = blockIdx.x * 256 + threadIdx.x;
    int node = gid >> 3;
    int lane = threadIdx.x & 7;
    if (node >= n) return;
    unsigned mask = __activemask();

    float4 v = *(reinterpret_cast<const float4*>(agg + (size_t)node * 32) + lane);
    v.x = fmaxf(v.x, 0.f); v.y = fmaxf(v.y, 0.f);
    v.z = fmaxf(v.z, 0.f); v.w = fmaxf(v.w, 0.f);

    float ss = v.x * v.x + v.y * v.y + v.z * v.z + v.w * v.w;
    ss += __shfl_xor_sync(mask, ss, 1);
    ss += __shfl_xor_sync(mask, ss, 2);
    ss += __shfl_xor_sync(mask, ss, 4);

    float nv = fmaxf(sqrtf(ss), EPSF);
    float rinv = 1.0f / nv;
    if (lane == 0) {
        float inv = 1.0f / fmaxf(denom[node], EPSF);
        normv[node] = nv * inv;
    }

    __half2 h0 = __floats2half2_rn(v.x * rinv, v.y * rinv);
    __half2 h1 = __floats2half2_rn(v.z * rinv, v.w * rinv);
    uint2 pk;
    pk.x = *reinterpret_cast<unsigned*>(&h0);
    pk.y = *reinterpret_cast<unsigned*>(&h1);
    *(reinterpret_cast<uint2*>(hn + (size_t)node * 32) + lane) = pk;
}

// ---------------------------------------------------------------------------
// Head, pair-blocked: threads (t, t^1) handle nodes (2p, 2p+1).
__global__ __launch_bounds__(256) void k_final(
    const float* __restrict__ agg, const float* __restrict__ denom,
    const float* __restrict__ w2, const float* __restrict__ b2,
    float* __restrict__ out, int n)
{
    __shared__ float w2t[32 * 64];
    __shared__ float b2s[64];
    for (int i = threadIdx.x; i < 2048; i += 256) {
        int j = i >> 5, k = i & 31;
        w2t[k * 64 + j] = w2[i];
    }
    for (int i = threadIdx.x; i < 64; i += 256) b2s[i] = b2[i];
    __syncthreads();

    int gid  = blockIdx.x * 256 + threadIdx.x;
    int pair = gid >> 1;
    int jh   = gid & 1;
    int n0   = pair * 2;
    int n1   = n0 + 1;
    if (n0 >= n) return;
    bool has1 = (n1 < n);

    float inv0 = 1.0f / fmaxf(denom[n0], EPSF);
    float inv1 = has1 ? (1.0f / fmaxf(denom[n1], EPSF)) : 0.f;

    float acc0[32], acc1[32];
    #pragma unroll
    for (int j = 0; j < 32; j++) {
        float b = b2s[jh * 32 + j];
        acc0[j] = b; acc1[j] = b;
    }

    const float4* h0 = reinterpret_cast<const float4*>(agg + (size_t)n0 * 32);
    const float4* h1 = reinterpret_cast<const float4*>(agg + (size_t)(has1 ? n1 : n0) * 32);

    #pragma unroll
    for (int k4 = 0; k4 < 8; k4++) {
        float4 hv0 = h0[k4];
        float4 hv1 = h1[k4];
        float hh0[4] = {fmaxf(hv0.x*inv0,0.f), fmaxf(hv0.y*inv0,0.f),
                        fmaxf(hv0.z*inv0,0.f), fmaxf(hv0.w*inv0,0.f)};
        float hh1[4] = {fmaxf(hv1.x*inv1,0.f), fmaxf(hv1.y*inv1,0.f),
                        fmaxf(hv1.z*inv1,0.f), fmaxf(hv1.w*inv1,0.f)};
        #pragma unroll
        for (int c = 0; c < 4; c++) {
            const float4* w4 = reinterpret_cast<const float4*>(
                &w2t[(k4 * 4 + c) * 64 + jh * 32]);
            float f0 = hh0[c], f1 = hh1[c];
            #pragma unroll
            for (int j4 = 0; j4 < 8; j4++) {
                float4 w = w4[j4];
                acc0[j4*4+0] += f0*w.x; acc0[j4*4+1] += f0*w.y;
                acc0[j4*4+2] += f0*w.z; acc0[j4*4+3] += f0*w.w;
                acc1[j4*4+0] += f1*w.x; acc1[j4*4+1] += f1*w.y;
                acc1[j4*4+2] += f1*w.z; acc1[j4*4+3] += f1*w.w;
            }
        }
    }

    float mx0 = acc0[0], mx1 = acc1[0];
    #pragma unroll
    for (int j = 1; j < 32; j++) { mx0 = fmaxf(mx0, acc0[j]); mx1 = fmaxf(mx1, acc1[j]); }
    mx0 = fmaxf(mx0, __shfl_xor_sync(FULLM, mx0, 1));
    mx1 = fmaxf(mx1, __shfl_xor_sync(FULLM, mx1, 1));

    float sum0 = 0.f, sum1 = 0.f;
    #pragma unroll
    for (int j = 0; j < 32; j++) {
        sum0 += __expf(acc0[j] - mx0);
        sum1 += __expf(acc1[j] - mx1);
    }
    sum0 += __shfl_xor_sync(FULLM, sum0, 1);
    sum1 += __shfl_xor_sync(FULLM, sum1, 1);

    float lse0 = mx0 + __logf(sum0);
    float lse1 = mx1 + __logf(sum1);

    float4* o0 = reinterpret_cast<float4*>(out + (size_t)n0 * 64 + jh * 32);
    #pragma unroll
    for (int j4 = 0; j4 < 8; j4++)
        o0[j4] = make_float4(acc0[j4*4]-lse0, acc0[j4*4+1]-lse0,
                             acc0[j4*4+2]-lse0, acc0[j4*4+3]-lse0);
    if (has1) {
        float4* o1 = reinterpret_cast<float4*>(out + (size_t)n1 * 64 + jh * 32);
        #pragma unroll
        for (int j4 = 0; j4 < 8; j4++)
            o1[j4] = make_float4(acc1[j4*4]-lse1, acc1[j4*4+1]-lse1,
                                 acc1[j4*4+2]-lse1, acc1[j4*4+3]-lse1);
    }
}

// ---------------------------------------------------------------------------
extern "C" void kernel_launch(void* const* d_in, const int* in_sizes, int n_in,
                              void* d_out, int out_size)
{
    const float* feat  = (const float*)d_in[0];
    const int*   src   = (const int*)d_in[1];
    const int*   dst   = (const int*)d_in[2];
    const float* w1    = (const float*)d_in[3];
    const float* b1    = (const float*)d_in[4];
    const float* betas = (const float*)d_in[5];
    const float* w2    = (const float*)d_in[6];
    const float* b2    = (const float*)d_in[7];
    float*       out   = (float*)d_out;

    const int n  = in_sizes[0] / 128;   // 100000
    const int ne = in_sizes[1];         // 1600000

    float *aggA, *aggB, *normv, *denA, *denB;
    __half *hnA, *hnB;
    cudaGetSymbolAddress((void**)&aggA,  g_aggA);
    cudaGetSymbolAddress((void**)&aggB,  g_aggB);
    cudaGetSymbolAddress((void**)&hnA,   g_hnA);
    cudaGetSymbolAddress((void**)&hnB,   g_hnB);
    cudaGetSymbolAddress((void**)&normv, g_norm);
    cudaGetSymbolAddress((void**)&denA,  g_denomA);
    cudaGetSymbolAddress((void**)&denB,  g_denomB);

    const int TB = 256;
    const int ngroups = (ne + 3) / 4;
    dim3 gN((n + TB - 1) / TB);
    dim3 gN8(((size_t)n * 8 + TB - 1) / TB);
    dim3 gG8(((size_t)ngroups * 8 + TB - 1) / TB);

    // Invariant: aggA/denA zero here (zero-init at load; re-zeroed by edge-1
    // prologue each invocation). aggB/denB zeroed by edge-0 prologue.

    // K1: hn0/norm0 (pair-blocked HFMA2)
    k_gemm1<<<gN, TB>>>(feat, w1, b1, hnA, normv, n);

    // ---- layer 0: hnA -> aggA/denA ; prologue zeroes aggB/denB ----
    k_edge_fused<<<gG8, TB>>>(src, dst, hnA, normv, betas, 0, denA, aggA,
                              aggB, denB, n, ne);
    k_norm_mid<<<gN8, TB>>>(aggA, denA, hnB, normv, n);

    // ---- layer 1: hnB -> aggB/denB ; prologue re-zeroes aggA/denA ----
    k_edge_fused<<<gG8, TB>>>(src, dst, hnB, normv, betas, 1, denB, aggB,
                              aggA, denA, n, ne);

    // Head (pair-blocked)
    k_final<<<gN, TB>>>(aggB, denB, w2, b2, out, n);
}